// round 15
// baseline (speedup 1.0000x reference)
#include <cuda_runtime.h>
#include <cuda_fp16.h>
#include <cstdint>

// Problem constants: B=8, N=2048, D=256, HEAD=8, ATT=32
#define NROWS 16384   // B*N
#define DMODEL 256

// Scratch (allocation-free rule: device globals)
__device__ __align__(16) __half g_AOh[NROWS * DMODEL];  // attention out, fp16
__device__ __align__(16) __half g_Qh[NROWS * DMODEL];   // fp16, pre-scaled log2e/sqrt(32)
__device__ __align__(16) __half g_Kh[NROWS * DMODEL];   // fp16
__device__ __align__(16) __half g_Vh[NROWS * DMODEL];   // fp16
__device__ __align__(16) __half g_Wh[4 * DMODEL * DMODEL];

// ========================= PTX helpers (compute_100-safe) ==================
__device__ __forceinline__ uint32_t smem_u32(const void* p) {
    uint32_t a;
    asm("{ .reg .u64 t; cvta.to.shared.u64 t, %1; cvt.u32.u64 %0, t; }"
        : "=r"(a) : "l"(p));
    return a;
}

#define LDSM_X4(r, addr) \
    asm volatile("ldmatrix.sync.aligned.m8n8.x4.shared.b16 {%0,%1,%2,%3}, [%4];" \
        : "=r"((r)[0]), "=r"((r)[1]), "=r"((r)[2]), "=r"((r)[3]) : "r"(addr))

#define LDSM_X4_T(r, addr) \
    asm volatile("ldmatrix.sync.aligned.m8n8.x4.trans.shared.b16 {%0,%1,%2,%3}, [%4];" \
        : "=r"((r)[0]), "=r"((r)[1]), "=r"((r)[2]), "=r"((r)[3]) : "r"(addr))

#define MMA16816(d, a, b) \
    asm volatile("mma.sync.aligned.m16n8k16.row.col.f32.f16.f16.f32 " \
        "{%0,%1,%2,%3}, {%4,%5,%6,%7}, {%8,%9}, {%0,%1,%2,%3};" \
        : "+f"((d)[0]), "+f"((d)[1]), "+f"((d)[2]), "+f"((d)[3]) \
        : "r"((a)[0]), "r"((a)[1]), "r"((a)[2]), "r"((a)[3]), \
          "r"((b)[0]), "r"((b)[1]))

#define CP_ASYNC16(dst, src) \
    asm volatile("cp.async.cg.shared.global [%0], [%1], 16;" \
        :: "r"(dst), "l"(src) : "memory")
#define CP_COMMIT() asm volatile("cp.async.commit_group;" ::: "memory")
#define CP_WAIT0()  asm volatile("cp.async.wait_group 0;" ::: "memory")
#define CP_WAIT1()  asm volatile("cp.async.wait_group 1;" ::: "memory")

__device__ __forceinline__ uint32_t pack_h(float x, float y) {
    __half2 h = __floats2half2_rn(x, y);
    return *reinterpret_cast<uint32_t*>(&h);
}
__device__ __forceinline__ float ex2f(float x) {
    float y;
    asm("ex2.approx.f32 %0, %1;" : "=f"(y) : "f"(x));
    return y;
}
// packed fp16 2^x: argument pair -> P pair (already MMA-ready)
__device__ __forceinline__ uint32_t ex2_h2(float x, float y) {
    __half2 a = __floats2half2_rn(x, y);
    uint32_t au = *reinterpret_cast<uint32_t*>(&a), pu;
    asm("ex2.approx.f16x2 %0, %1;" : "=r"(pu) : "r"(au));
    return pu;
}
__device__ __forceinline__ __half2 u2h2(uint32_t u) {
    return *reinterpret_cast<__half2*>(&u);
}

// ============================ weight convert ===============================
__global__ void convert_w_kernel(const float* __restrict__ W0, const float* __restrict__ W1,
                                 const float* __restrict__ W2, const float* __restrict__ W3,
                                 __half* __restrict__ hi)
{
    int i = blockIdx.x * 256 + threadIdx.x;
    int m = blockIdx.y;
    const float* src = (m == 0) ? W0 : (m == 1) ? W1 : (m == 2) ? W2 : W3;
    hi[m * 65536 + i] = __float2half_rn(src[i]);
}

// ==================== pipelined mma.sync fp16 GEMM (QKV) ===================
#define GSM_AH   0
#define GSM_WB(b) (10240 + (b) * 10240)
#define GSM_TOTAL 30720

#define GEMM_MAINLOOP(APTR, WHI)                                                   \
    float4 pa[4];                                                                  \
    const int ar  = tid >> 1;                                                      \
    const int acb = (tid & 1) * 16;                                                \
    _Pragma("unroll")                                                              \
    for (int g = 0; g < 2; g++) {                                                  \
        int s = tid + g * 256, r = s >> 2, c8 = (s & 3) * 8;                       \
        CP_ASYNC16(sb + GSM_WB(0) + (r * 40 + c8) * 2,                             \
                   (WHI) + (size_t)(n0 + r) * 256 + c8);                           \
    }                                                                              \
    CP_COMMIT();                                                                   \
    _Pragma("unroll")                                                              \
    for (int it = 0; it < 4; it++)                                                 \
        pa[it] = *(const float4*)((APTR) + (size_t)(m0 + ar) * 256 + acb + it * 4);\
    const uint32_t wfoff = ((wn + (((lane >> 4) & 1) << 3) + (lane & 7)) * 40      \
                           + (((lane >> 3) & 1) << 3)) * 2;                        \
    for (int chunk = 0; chunk < 8; chunk++) {                                      \
        const int kk = chunk * 32;                                                 \
        const uint32_t wb = sb + GSM_WB(chunk & 1);                                \
        __syncthreads();                                                           \
        {                                                                          \
            uint32_t p[8];                                                         \
            _Pragma("unroll")                                                      \
            for (int q = 0; q < 4; q++) {                                          \
                p[2 * q]     = pack_h(pa[q].x, pa[q].y);                           \
                p[2 * q + 1] = pack_h(pa[q].z, pa[q].w);                           \
            }                                                                      \
            *(uint4*)(smem + GSM_AH + (ar * 40 + acb) * 2) =                       \
                make_uint4(p[0], p[1], p[2], p[3]);                                \
            *(uint4*)(smem + GSM_AH + (ar * 40 + acb) * 2 + 16) =                  \
                make_uint4(p[4], p[5], p[6], p[7]);                                \
        }                                                                          \
        if (chunk < 7) {                                                           \
            const uint32_t wn2 = sb + GSM_WB((chunk + 1) & 1);                     \
            _Pragma("unroll")                                                      \
            for (int g = 0; g < 2; g++) {                                          \
                int s = tid + g * 256, r = s >> 2, c8 = (s & 3) * 8;               \
                CP_ASYNC16(wn2 + (r * 40 + c8) * 2,                                \
                           (WHI) + (size_t)(n0 + r) * 256 + kk + 32 + c8);         \
            }                                                                      \
            CP_COMMIT();                                                           \
            _Pragma("unroll")                                                      \
            for (int it = 0; it < 4; it++)                                         \
                pa[it] = *(const float4*)((APTR) + (size_t)(m0 + ar) * 256         \
                                          + kk + 32 + acb + it * 4);               \
            CP_WAIT1();                                                            \
        } else {                                                                   \
            CP_WAIT0();                                                            \
        }                                                                          \
        __syncthreads();                                                           \
        _Pragma("unroll")                                                          \
        for (int ks = 0; ks < 32; ks += 16) {                                      \
            uint32_t ah[4][4];                                                     \
            const int arow = lane & 15;                                            \
            const int acol = ks + ((lane >> 4) << 3);                              \
            _Pragma("unroll")                                                      \
            for (int i = 0; i < 4; i++)                                            \
                LDSM_X4(ah[i], sb + GSM_AH + ((wm + i * 16 + arow) * 40 + acol) * 2); \
            _Pragma("unroll")                                                      \
            for (int jp = 0; jp < 2; jp++) {                                       \
                uint32_t w4[4];                                                    \
                LDSM_X4(w4, wb + wfoff + (jp * 16 * 40 + ks) * 2);                 \
                _Pragma("unroll")                                                  \
                for (int i = 0; i < 4; i++) {                                      \
                    MMA16816(acc[i][2 * jp],     ah[i], (&w4[0]));                 \
                    MMA16816(acc[i][2 * jp + 1], ah[i], (&w4[2]));                 \
                }                                                                  \
            }                                                                      \
        }                                                                          \
    }

// --- fused QKV projection: outputs fp16 (Q pre-scaled by log2e/sqrt(32)) ---
__global__ __launch_bounds__(256, 2)
void gemm_qkv_kernel(const float* __restrict__ query, const float* __restrict__ key,
                     const float* __restrict__ value,
                     const __half* __restrict__ Wh_all,
                     const float* __restrict__ bq, const float* __restrict__ bk,
                     const float* __restrict__ bv,
                     __half* __restrict__ Qh, __half* __restrict__ Kh,
                     __half* __restrict__ Vh)
{
    extern __shared__ char smem[];
    const uint32_t sb = smem_u32(smem);
    const int tid  = threadIdx.x;
    const int wid  = tid >> 5;
    const int lane = tid & 31;
    const int m0 = blockIdx.y * 128;
    const int n0 = blockIdx.x * 128;
    const int wm = (wid >> 2) * 64;
    const int wn = (wid & 3) * 32;
    const int z = blockIdx.z;

    const float* A   = (z == 0) ? query : (z == 1) ? key : value;
    const float* bia = (z == 0) ? bq    : (z == 1) ? bk  : bv;
    const __half* Whi = Wh_all + (size_t)z * 65536;
    __half* Oh = (z == 0) ? Qh : (z == 1) ? Kh : Vh;
    // Q scale = log2(e)/sqrt(32): softmax done in base-2 units
    const float oscale = (z == 0) ? 0.2550348652153015f : 1.0f;

    float acc[4][4][4] = {};
    GEMM_MAINLOOP(A, Whi)

    const int r0 = lane >> 2;
    const int cp = (lane & 3) * 2;
    #pragma unroll
    for (int i = 0; i < 4; i++)
        #pragma unroll
        for (int j = 0; j < 4; j++) {
            int col = n0 + wn + j * 8 + cp;
            float2 bb = *(const float2*)(bia + col);
            int row = m0 + wm + i * 16 + r0;
            *(uint32_t*)(Oh + (size_t)row * 256 + col) =
                pack_h((acc[i][j][0] + bb.x) * oscale, (acc[i][j][1] + bb.y) * oscale);
            *(uint32_t*)(Oh + (size_t)(row + 8) * 256 + col) =
                pack_h((acc[i][j][2] + bb.x) * oscale, (acc[i][j][3] + bb.y) * oscale);
        }
}

// --- output projection: A is fp16 (attention output), pure cp.async staging ---
#define OSM_AB(b) ((b) * 20480)
#define OSM_WB(b) ((b) * 20480 + 10240)
#define OSM_TOTAL 40960

__global__ __launch_bounds__(256, 2)
void gemm_out_kernel(const __half* __restrict__ A,
                     const __half* __restrict__ Whi,
                     const float* __restrict__ bias,
                     float* __restrict__ C)
{
    extern __shared__ char smem[];
    const uint32_t sb = smem_u32(smem);
    const int tid  = threadIdx.x;
    const int wid  = tid >> 5;
    const int lane = tid & 31;
    const int m0 = blockIdx.y * 128;
    const int n0 = blockIdx.x * 128;
    const int wm = (wid >> 2) * 64;
    const int wn = (wid & 3) * 32;

    float acc[4][4][4] = {};

    #pragma unroll
    for (int g = 0; g < 2; g++) {
        int s = tid + g * 256, r = s >> 2, c8 = (s & 3) * 8;
        CP_ASYNC16(sb + OSM_AB(0) + (r * 40 + c8) * 2, A   + (size_t)(m0 + r) * 256 + c8);
        CP_ASYNC16(sb + OSM_WB(0) + (r * 40 + c8) * 2, Whi + (size_t)(n0 + r) * 256 + c8);
    }
    CP_COMMIT();

    const uint32_t wfoff = ((wn + (((lane >> 4) & 1) << 3) + (lane & 7)) * 40
                           + (((lane >> 3) & 1) << 3)) * 2;

    for (int chunk = 0; chunk < 8; chunk++) {
        const int kk = chunk * 32;
        __syncthreads();
        if (chunk < 7) {
            const uint32_t ab = sb + OSM_AB((chunk + 1) & 1);
            const uint32_t wb2 = sb + OSM_WB((chunk + 1) & 1);
            #pragma unroll
            for (int g = 0; g < 2; g++) {
                int s = tid + g * 256, r = s >> 2, c8 = (s & 3) * 8;
                CP_ASYNC16(ab  + (r * 40 + c8) * 2, A   + (size_t)(m0 + r) * 256 + kk + 32 + c8);
                CP_ASYNC16(wb2 + (r * 40 + c8) * 2, Whi + (size_t)(n0 + r) * 256 + kk + 32 + c8);
            }
            CP_COMMIT();
            CP_WAIT1();
        } else {
            CP_WAIT0();
        }
        __syncthreads();

        const uint32_t ab = sb + OSM_AB(chunk & 1);
        const uint32_t wb = sb + OSM_WB(chunk & 1);
        #pragma unroll
        for (int ks = 0; ks < 32; ks += 16) {
            uint32_t ah[4][4];
            const int arow = lane & 15;
            const int acol = ks + ((lane >> 4) << 3);
            #pragma unroll
            for (int i = 0; i < 4; i++)
                LDSM_X4(ah[i], ab + ((wm + i * 16 + arow) * 40 + acol) * 2);
            #pragma unroll
            for (int jp = 0; jp < 2; jp++) {
                uint32_t w4[4];
                LDSM_X4(w4, wb + wfoff + (jp * 16 * 40 + ks) * 2);
                #pragma unroll
                for (int i = 0; i < 4; i++) {
                    MMA16816(acc[i][2 * jp],     ah[i], (&w4[0]));
                    MMA16816(acc[i][2 * jp + 1], ah[i], (&w4[2]));
                }
            }
        }
    }

    const int r0 = lane >> 2;
    const int cp = (lane & 3) * 2;
    #pragma unroll
    for (int i = 0; i < 4; i++)
        #pragma unroll
        for (int j = 0; j < 4; j++) {
            int col = n0 + wn + j * 8 + cp;
            float2 bb = *(const float2*)(bias + col);
            int row = m0 + wm + i * 16 + r0;
            float2 o0 = make_float2(acc[i][j][0] + bb.x, acc[i][j][1] + bb.y);
            *(float2*)(C + (size_t)row * 256 + col) = o0;
            float2 o1 = make_float2(acc[i][j][2] + bb.x, acc[i][j][3] + bb.y);
            *(float2*)(C + (size_t)(row + 8) * 256 + col) = o1;
        }
}

// ====================== mma.sync flash attention (fp16) ====================
// SUPER-ITERATIONS: 2 KV tiles per barrier pair + cp.async group. ntiles is
// always even (2*tq+2), so nsuper = tq+1 super-steps, each double-buffered
// (20480 B per super-buffer: 2 tiles x {K 5120, V 5120}).
// Dynamic smem: Qh @ 0 (10240); super-buf b @ 10240+b*20480. Total 51200.
#define ASM_QH 0
#define ASM_SB(b) (10240 + (b) * 20480)
#define ASM_TOTAL 51200

__global__ __launch_bounds__(256, 2)
void attn_mma_kernel(const __half* __restrict__ Qh_g,
                     const __half* __restrict__ Kh_g,
                     const __half* __restrict__ Vh_g,
                     __half* __restrict__ Og)
{
    extern __shared__ char smem[];
    const uint32_t sb = smem_u32(smem);
    const int tid  = threadIdx.x;
    const int wid  = tid >> 5;
    const int lane = tid & 31;
    const int tq = (int)gridDim.x - 1 - (int)blockIdx.x;   // long blocks first
    const int hb = blockIdx.y;
    const int h  = hb & 7;
    const int bb = hb >> 3;
    const size_t base = (size_t)bb * 2048 * 256 + (size_t)h * 32;
    const int qbase = tq * 128;
    __half* Ob = Og + base;

    const int nsuper = tq + 1;   // ntiles = 2*tq+2, two tiles per super-step

    // prologue: cp.async Q + tiles {0,1} -> super-buf 0, one group
    #pragma unroll
    for (int g = 0; g < 2; g++) {
        int s = tid + g * 256, r = s >> 2, c8 = (s & 3) * 8;
        CP_ASYNC16(sb + ASM_QH + (r * 40 + c8) * 2,
                   Qh_g + base + (size_t)(qbase + r) * 256 + c8);
    }
    {
        int r = tid >> 2, c8 = (tid & 3) * 8;
        #pragma unroll
        for (int sub = 0; sub < 2; sub++) {
            size_t src = base + (size_t)(sub * 64 + r) * 256 + c8;
            uint32_t dst = sb + ASM_SB(0) + sub * 10240 + (r * 40 + c8) * 2;
            CP_ASYNC16(dst,        Kh_g + src);
            CP_ASYNC16(dst + 5120, Vh_g + src);
        }
    }
    CP_COMMIT();

    uint32_t qh[2][4];
    float o[4][4] = {};
    float mrow[2] = {-1e30f, -1e30f};   // log2 units
    float lrow[2] = {0.0f, 0.0f};

    const uint32_t kfoff = (((((lane >> 4) & 1) << 3) + (lane & 7)) * 40
                           + (((lane >> 3) & 1) << 3)) * 2;
    const uint32_t vfoff = 5120u + ((lane & 15) * 40 + (((lane >> 4) & 1) << 3)) * 2;

    for (int u = 0; u < nsuper; u++) {
        __syncthreads();   // all warps done reading super-buf (u+1)&1 (step u-1)
        if (u + 1 < nsuper) {
            const uint32_t sbuf = sb + ASM_SB((u + 1) & 1);
            int r = tid >> 2, c8 = (tid & 3) * 8;
            #pragma unroll
            for (int sub = 0; sub < 2; sub++) {
                size_t src = base + (size_t)((2 * (u + 1) + sub) * 64 + r) * 256 + c8;
                uint32_t dst = sbuf + sub * 10240 + (r * 40 + c8) * 2;
                CP_ASYNC16(dst,        Kh_g + src);
                CP_ASYNC16(dst + 5120, Vh_g + src);
            }
            CP_COMMIT();
            CP_WAIT1();    // super-step u (and Q on u==0) landed
        } else {
            CP_WAIT0();
        }
        __syncthreads();

        if (u == 0) {      // resident Q fragments
            const int arow = lane & 15;
            const int aco  = ((lane >> 4) << 3);
            #pragma unroll
            for (int ks = 0; ks < 2; ks++)
                LDSM_X4(qh[ks], sb + ASM_QH + ((wid * 16 + arow) * 40 + ks * 16 + aco) * 2);
        }

        #pragma unroll
        for (int sub = 0; sub < 2; sub++) {
            const int jt = 2 * u + sub;
            // skip warps fully masked by causality
            if (jt * 64 > qbase + wid * 16 + 15) continue;

            const uint32_t kv = sb + ASM_SB(u & 1) + sub * 10240;

            // ---- S = Q @ K^T (single fp16 pass; logits in log2 units) ----
            float s[8][4] = {};
            #pragma unroll
            for (int ks = 0; ks < 2; ks++) {
                #pragma unroll
                for (int jp = 0; jp < 4; jp++) {
                    uint32_t k4[4];
                    LDSM_X4(k4, kv + kfoff + (jp * 16 * 40 + ks * 16) * 2);
                    MMA16816(s[2 * jp],     qh[ks], (&k4[0]));
                    MMA16816(s[2 * jp + 1], qh[ks], (&k4[2]));
                }
            }

            // ---- causal mask (diagonal region only) ----
            if (jt >= 2 * tq) {
                const int row0 = qbase + wid * 16 + (lane >> 2);
                #pragma unroll
                for (int j = 0; j < 8; j++) {
                    int col = jt * 64 + j * 8 + (lane & 3) * 2;
                    if (col     > row0)     s[j][0] = -1e30f;
                    if (col + 1 > row0)     s[j][1] = -1e30f;
                    if (col     > row0 + 8) s[j][2] = -1e30f;
                    if (col + 1 > row0 + 8) s[j][3] = -1e30f;
                }
            }

            // ---- online softmax (base-2; P via ex2.approx.f16x2) ----
            uint32_t p2[2][8];
            #pragma unroll
            for (int hf = 0; hf < 2; hf++) {
                const int a0 = 2 * hf, a1 = 2 * hf + 1;
                float mj[8];
                #pragma unroll
                for (int j = 0; j < 8; j++) mj[j] = fmaxf(s[j][a0], s[j][a1]);
                mj[0] = fmaxf(mj[0], mj[1]); mj[2] = fmaxf(mj[2], mj[3]);
                mj[4] = fmaxf(mj[4], mj[5]); mj[6] = fmaxf(mj[6], mj[7]);
                mj[0] = fmaxf(mj[0], mj[2]); mj[4] = fmaxf(mj[4], mj[6]);
                float mt = fmaxf(mj[0], mj[4]);
                mt = fmaxf(mt, __shfl_xor_sync(0xffffffffu, mt, 1));
                mt = fmaxf(mt, __shfl_xor_sync(0xffffffffu, mt, 2));
                float mnew  = fmaxf(mrow[hf], mt);
                float alpha = ex2f(mrow[hf] - mnew);
                #pragma unroll
                for (int j = 0; j < 8; j++)
                    p2[hf][j] = ex2_h2(s[j][a0] - mnew, s[j][a1] - mnew);
                __half2 t0 = __hadd2(u2h2(p2[hf][0]), u2h2(p2[hf][1]));
                __half2 t1 = __hadd2(u2h2(p2[hf][2]), u2h2(p2[hf][3]));
                __half2 t2 = __hadd2(u2h2(p2[hf][4]), u2h2(p2[hf][5]));
                __half2 t3 = __hadd2(u2h2(p2[hf][6]), u2h2(p2[hf][7]));
                t0 = __hadd2(t0, t1); t2 = __hadd2(t2, t3);
                t0 = __hadd2(t0, t2);
                float ls = __low2float(t0) + __high2float(t0);
                ls += __shfl_xor_sync(0xffffffffu, ls, 1);
                ls += __shfl_xor_sync(0xffffffffu, ls, 2);
                mrow[hf] = mnew;
                lrow[hf] = lrow[hf] * alpha + ls;
                #pragma unroll
                for (int j = 0; j < 4; j++) {
                    o[j][a0] *= alpha;
                    o[j][a1] *= alpha;
                }
            }

            // ---- O += P @ V (single pass; P already packed) ----
            #pragma unroll
            for (int t = 0; t < 4; t++) {
                uint32_t ph[4];
                ph[0] = p2[0][2 * t];
                ph[1] = p2[1][2 * t];
                ph[2] = p2[0][2 * t + 1];
                ph[3] = p2[1][2 * t + 1];

                #pragma unroll
                for (int jp = 0; jp < 2; jp++) {
                    uint32_t v4[4];
                    LDSM_X4_T(v4, kv + vfoff + (t * 16 * 40 + jp * 16) * 2);
                    MMA16816(o[2 * jp],     ph, (&v4[0]));
                    MMA16816(o[2 * jp + 1], ph, (&v4[2]));
                }
            }
        }
    }

    // ---- normalize + store (fp16) ----
    const float inv0 = 1.0f / lrow[0];
    const float inv1 = 1.0f / lrow[1];
    const int row = qbase + wid * 16 + (lane >> 2);
    #pragma unroll
    for (int j = 0; j < 4; j++) {
        int col = j * 8 + (lane & 3) * 2;
        *(uint32_t*)(Ob + (size_t)row * 256 + col) =
            pack_h(o[j][0] * inv0, o[j][1] * inv0);
        *(uint32_t*)(Ob + (size_t)(row + 8) * 256 + col) =
            pack_h(o[j][2] * inv1, o[j][3] * inv1);
    }
}

// ---------------------------------------------------------------------------
extern "C" void kernel_launch(void* const* d_in, const int* in_sizes, int n_in,
                              void* d_out, int out_size)
{
    const float* query = (const float*)d_in[0];
    const float* key   = (const float*)d_in[1];
    const float* value = (const float*)d_in[2];
    const float* Wq    = (const float*)d_in[3];
    const float* bq    = (const float*)d_in[4];
    const float* Wk    = (const float*)d_in[5];
    const float* bk    = (const float*)d_in[6];
    const float* Wv    = (const float*)d_in[7];
    const float* bv    = (const float*)d_in[8];
    const float* Wo    = (const float*)d_in[9];
    const float* bo    = (const float*)d_in[10];
    float* out = (float*)d_out;

    __half *AOh, *Qh, *Kh, *Vh, *Wh;
    cudaGetSymbolAddress((void**)&AOh, g_AOh);
    cudaGetSymbolAddress((void**)&Qh,  g_Qh);
    cudaGetSymbolAddress((void**)&Kh,  g_Kh);
    cudaGetSymbolAddress((void**)&Vh,  g_Vh);
    cudaGetSymbolAddress((void**)&Wh,  g_Wh);

    cudaFuncSetAttribute(gemm_qkv_kernel,
                         cudaFuncAttributeMaxDynamicSharedMemorySize, GSM_TOTAL);
    cudaFuncSetAttribute(gemm_out_kernel,
                         cudaFuncAttributeMaxDynamicSharedMemorySize, OSM_TOTAL);
    cudaFuncSetAttribute(attn_mma_kernel,
                         cudaFuncAttributeMaxDynamicSharedMemorySize, ASM_TOTAL);

    convert_w_kernel<<<dim3(256, 4), 256>>>(Wq, Wk, Wv, Wo, Wh);

    gemm_qkv_kernel<<<dim3(2, 128, 3), 256, GSM_TOTAL>>>(
        query, key, value, Wh, bq, bk, bv, Qh, Kh, Vh);

    attn_mma_kernel<<<dim3(16, 64), 256, ASM_TOTAL>>>(Qh, Kh, Vh, AOh);

    gemm_out_kernel<<<dim3(2, 128), 256, OSM_TOTAL>>>(
        AOh, Wh + 3 * 65536, bo, out);
}

// round 17
// speedup vs baseline: 1.0150x; 1.0150x over previous
#include <cuda_runtime.h>
#include <cuda_fp16.h>
#include <cstdint>

// Problem constants: B=8, N=2048, D=256, HEAD=8, ATT=32
#define NROWS 16384   // B*N
#define DMODEL 256

// Scratch (allocation-free rule: device globals)
__device__ __align__(16) __half g_AOh[NROWS * DMODEL];  // attention out, fp16
__device__ __align__(16) __half g_Qh[NROWS * DMODEL];   // fp16, pre-scaled log2e/sqrt(32)
__device__ __align__(16) __half g_Kh[NROWS * DMODEL];   // fp16
__device__ __align__(16) __half g_Vh[NROWS * DMODEL];   // fp16
__device__ __align__(16) __half g_Wh[4 * DMODEL * DMODEL];

// ========================= PTX helpers (compute_100-safe) ==================
__device__ __forceinline__ uint32_t smem_u32(const void* p) {
    uint32_t a;
    asm("{ .reg .u64 t; cvta.to.shared.u64 t, %1; cvt.u32.u64 %0, t; }"
        : "=r"(a) : "l"(p));
    return a;
}

#define LDSM_X4(r, addr) \
    asm volatile("ldmatrix.sync.aligned.m8n8.x4.shared.b16 {%0,%1,%2,%3}, [%4];" \
        : "=r"((r)[0]), "=r"((r)[1]), "=r"((r)[2]), "=r"((r)[3]) : "r"(addr))

#define LDSM_X4_T(r, addr) \
    asm volatile("ldmatrix.sync.aligned.m8n8.x4.trans.shared.b16 {%0,%1,%2,%3}, [%4];" \
        : "=r"((r)[0]), "=r"((r)[1]), "=r"((r)[2]), "=r"((r)[3]) : "r"(addr))

#define MMA16816(d, a, b) \
    asm volatile("mma.sync.aligned.m16n8k16.row.col.f32.f16.f16.f32 " \
        "{%0,%1,%2,%3}, {%4,%5,%6,%7}, {%8,%9}, {%0,%1,%2,%3};" \
        : "+f"((d)[0]), "+f"((d)[1]), "+f"((d)[2]), "+f"((d)[3]) \
        : "r"((a)[0]), "r"((a)[1]), "r"((a)[2]), "r"((a)[3]), \
          "r"((b)[0]), "r"((b)[1]))

#define CP_ASYNC16(dst, src) \
    asm volatile("cp.async.cg.shared.global [%0], [%1], 16;" \
        :: "r"(dst), "l"(src) : "memory")
#define CP_COMMIT() asm volatile("cp.async.commit_group;" ::: "memory")
#define CP_WAIT0()  asm volatile("cp.async.wait_group 0;" ::: "memory")
#define CP_WAIT1()  asm volatile("cp.async.wait_group 1;" ::: "memory")

__device__ __forceinline__ uint32_t pack_h(float x, float y) {
    __half2 h = __floats2half2_rn(x, y);
    return *reinterpret_cast<uint32_t*>(&h);
}
__device__ __forceinline__ float ex2f(float x) {
    float y;
    asm("ex2.approx.f32 %0, %1;" : "=f"(y) : "f"(x));
    return y;
}
// packed fp16 2^x: argument pair -> P pair (already MMA-ready)
__device__ __forceinline__ uint32_t ex2_h2(float x, float y) {
    __half2 a = __floats2half2_rn(x, y);
    uint32_t au = *reinterpret_cast<uint32_t*>(&a), pu;
    asm("ex2.approx.f16x2 %0, %1;" : "=r"(pu) : "r"(au));
    return pu;
}
__device__ __forceinline__ __half2 u2h2(uint32_t u) {
    return *reinterpret_cast<__half2*>(&u);
}

// ============================ weight convert ===============================
__global__ void convert_w_kernel(const float* __restrict__ W0, const float* __restrict__ W1,
                                 const float* __restrict__ W2, const float* __restrict__ W3,
                                 __half* __restrict__ hi)
{
    int i = blockIdx.x * 256 + threadIdx.x;
    int m = blockIdx.y;
    const float* src = (m == 0) ? W0 : (m == 1) ? W1 : (m == 2) ? W2 : W3;
    hi[m * 65536 + i] = __float2half_rn(src[i]);
}

// ==================== pipelined mma.sync fp16 GEMM (QKV) ===================
#define GSM_AH   0
#define GSM_WB(b) (10240 + (b) * 10240)
#define GSM_TOTAL 30720

#define GEMM_MAINLOOP(APTR, WHI)                                                   \
    float4 pa[4];                                                                  \
    const int ar  = tid >> 1;                                                      \
    const int acb = (tid & 1) * 16;                                                \
    _Pragma("unroll")                                                              \
    for (int g = 0; g < 2; g++) {                                                  \
        int s = tid + g * 256, r = s >> 2, c8 = (s & 3) * 8;                       \
        CP_ASYNC16(sb + GSM_WB(0) + (r * 40 + c8) * 2,                             \
                   (WHI) + (size_t)(n0 + r) * 256 + c8);                           \
    }                                                                              \
    CP_COMMIT();                                                                   \
    _Pragma("unroll")                                                              \
    for (int it = 0; it < 4; it++)                                                 \
        pa[it] = *(const float4*)((APTR) + (size_t)(m0 + ar) * 256 + acb + it * 4);\
    const uint32_t wfoff = ((wn + (((lane >> 4) & 1) << 3) + (lane & 7)) * 40      \
                           + (((lane >> 3) & 1) << 3)) * 2;                        \
    for (int chunk = 0; chunk < 8; chunk++) {                                      \
        const int kk = chunk * 32;                                                 \
        const uint32_t wb = sb + GSM_WB(chunk & 1);                                \
        __syncthreads();                                                           \
        {                                                                          \
            uint32_t p[8];                                                         \
            _Pragma("unroll")                                                      \
            for (int q = 0; q < 4; q++) {                                          \
                p[2 * q]     = pack_h(pa[q].x, pa[q].y);                           \
                p[2 * q + 1] = pack_h(pa[q].z, pa[q].w);                           \
            }                                                                      \
            *(uint4*)(smem + GSM_AH + (ar * 40 + acb) * 2) =                       \
                make_uint4(p[0], p[1], p[2], p[3]);                                \
            *(uint4*)(smem + GSM_AH + (ar * 40 + acb) * 2 + 16) =                  \
                make_uint4(p[4], p[5], p[6], p[7]);                                \
        }                                                                          \
        if (chunk < 7) {                                                           \
            const uint32_t wn2 = sb + GSM_WB((chunk + 1) & 1);                     \
            _Pragma("unroll")                                                      \
            for (int g = 0; g < 2; g++) {                                          \
                int s = tid + g * 256, r = s >> 2, c8 = (s & 3) * 8;               \
                CP_ASYNC16(wn2 + (r * 40 + c8) * 2,                                \
                           (WHI) + (size_t)(n0 + r) * 256 + kk + 32 + c8);         \
            }                                                                      \
            CP_COMMIT();                                                           \
            _Pragma("unroll")                                                      \
            for (int it = 0; it < 4; it++)                                         \
                pa[it] = *(const float4*)((APTR) + (size_t)(m0 + ar) * 256         \
                                          + kk + 32 + acb + it * 4);               \
            CP_WAIT1();                                                            \
        } else {                                                                   \
            CP_WAIT0();                                                            \
        }                                                                          \
        __syncthreads();                                                           \
        _Pragma("unroll")                                                          \
        for (int ks = 0; ks < 32; ks += 16) {                                      \
            uint32_t ah[4][4];                                                     \
            const int arow = lane & 15;                                            \
            const int acol = ks + ((lane >> 4) << 3);                              \
            _Pragma("unroll")                                                      \
            for (int i = 0; i < 4; i++)                                            \
                LDSM_X4(ah[i], sb + GSM_AH + ((wm + i * 16 + arow) * 40 + acol) * 2); \
            _Pragma("unroll")                                                      \
            for (int jp = 0; jp < 2; jp++) {                                       \
                uint32_t w4[4];                                                    \
                LDSM_X4(w4, wb + wfoff + (jp * 16 * 40 + ks) * 2);                 \
                _Pragma("unroll")                                                  \
                for (int i = 0; i < 4; i++) {                                      \
                    MMA16816(acc[i][2 * jp],     ah[i], (&w4[0]));                 \
                    MMA16816(acc[i][2 * jp + 1], ah[i], (&w4[2]));                 \
                }                                                                  \
            }                                                                      \
        }                                                                          \
    }

// --- fused QKV projection: outputs fp16 (Q pre-scaled by log2e/sqrt(32)) ---
__global__ __launch_bounds__(256, 2)
void gemm_qkv_kernel(const float* __restrict__ query, const float* __restrict__ key,
                     const float* __restrict__ value,
                     const __half* __restrict__ Wh_all,
                     const float* __restrict__ bq, const float* __restrict__ bk,
                     const float* __restrict__ bv,
                     __half* __restrict__ Qh, __half* __restrict__ Kh,
                     __half* __restrict__ Vh)
{
    extern __shared__ char smem[];
    const uint32_t sb = smem_u32(smem);
    const int tid  = threadIdx.x;
    const int wid  = tid >> 5;
    const int lane = tid & 31;
    const int m0 = blockIdx.y * 128;
    const int n0 = blockIdx.x * 128;
    const int wm = (wid >> 2) * 64;
    const int wn = (wid & 3) * 32;
    const int z = blockIdx.z;

    const float* A   = (z == 0) ? query : (z == 1) ? key : value;
    const float* bia = (z == 0) ? bq    : (z == 1) ? bk  : bv;
    const __half* Whi = Wh_all + (size_t)z * 65536;
    __half* Oh = (z == 0) ? Qh : (z == 1) ? Kh : Vh;
    // Q scale = log2(e)/sqrt(32): softmax done in base-2 units
    const float oscale = (z == 0) ? 0.2550348652153015f : 1.0f;

    float acc[4][4][4] = {};
    GEMM_MAINLOOP(A, Whi)

    const int r0 = lane >> 2;
    const int cp = (lane & 3) * 2;
    #pragma unroll
    for (int i = 0; i < 4; i++)
        #pragma unroll
        for (int j = 0; j < 4; j++) {
            int col = n0 + wn + j * 8 + cp;
            float2 bb = *(const float2*)(bia + col);
            int row = m0 + wm + i * 16 + r0;
            *(uint32_t*)(Oh + (size_t)row * 256 + col) =
                pack_h((acc[i][j][0] + bb.x) * oscale, (acc[i][j][1] + bb.y) * oscale);
            *(uint32_t*)(Oh + (size_t)(row + 8) * 256 + col) =
                pack_h((acc[i][j][2] + bb.x) * oscale, (acc[i][j][3] + bb.y) * oscale);
        }
}

// --- output projection: A is fp16 (attention output), pure cp.async staging ---
#define OSM_AB(b) ((b) * 20480)
#define OSM_WB(b) ((b) * 20480 + 10240)
#define OSM_TOTAL 40960

__global__ __launch_bounds__(256, 2)
void gemm_out_kernel(const __half* __restrict__ A,
                     const __half* __restrict__ Whi,
                     const float* __restrict__ bias,
                     float* __restrict__ C)
{
    extern __shared__ char smem[];
    const uint32_t sb = smem_u32(smem);
    const int tid  = threadIdx.x;
    const int wid  = tid >> 5;
    const int lane = tid & 31;
    const int m0 = blockIdx.y * 128;
    const int n0 = blockIdx.x * 128;
    const int wm = (wid >> 2) * 64;
    const int wn = (wid & 3) * 32;

    float acc[4][4][4] = {};

    #pragma unroll
    for (int g = 0; g < 2; g++) {
        int s = tid + g * 256, r = s >> 2, c8 = (s & 3) * 8;
        CP_ASYNC16(sb + OSM_AB(0) + (r * 40 + c8) * 2, A   + (size_t)(m0 + r) * 256 + c8);
        CP_ASYNC16(sb + OSM_WB(0) + (r * 40 + c8) * 2, Whi + (size_t)(n0 + r) * 256 + c8);
    }
    CP_COMMIT();

    const uint32_t wfoff = ((wn + (((lane >> 4) & 1) << 3) + (lane & 7)) * 40
                           + (((lane >> 3) & 1) << 3)) * 2;

    for (int chunk = 0; chunk < 8; chunk++) {
        const int kk = chunk * 32;
        __syncthreads();
        if (chunk < 7) {
            const uint32_t ab = sb + OSM_AB((chunk + 1) & 1);
            const uint32_t wb2 = sb + OSM_WB((chunk + 1) & 1);
            #pragma unroll
            for (int g = 0; g < 2; g++) {
                int s = tid + g * 256, r = s >> 2, c8 = (s & 3) * 8;
                CP_ASYNC16(ab  + (r * 40 + c8) * 2, A   + (size_t)(m0 + r) * 256 + kk + 32 + c8);
                CP_ASYNC16(wb2 + (r * 40 + c8) * 2, Whi + (size_t)(n0 + r) * 256 + kk + 32 + c8);
            }
            CP_COMMIT();
            CP_WAIT1();
        } else {
            CP_WAIT0();
        }
        __syncthreads();

        const uint32_t ab = sb + OSM_AB(chunk & 1);
        const uint32_t wb = sb + OSM_WB(chunk & 1);
        #pragma unroll
        for (int ks = 0; ks < 32; ks += 16) {
            uint32_t ah[4][4];
            const int arow = lane & 15;
            const int acol = ks + ((lane >> 4) << 3);
            #pragma unroll
            for (int i = 0; i < 4; i++)
                LDSM_X4(ah[i], ab + ((wm + i * 16 + arow) * 40 + acol) * 2);
            #pragma unroll
            for (int jp = 0; jp < 2; jp++) {
                uint32_t w4[4];
                LDSM_X4(w4, wb + wfoff + (jp * 16 * 40 + ks) * 2);
                #pragma unroll
                for (int i = 0; i < 4; i++) {
                    MMA16816(acc[i][2 * jp],     ah[i], (&w4[0]));
                    MMA16816(acc[i][2 * jp + 1], ah[i], (&w4[2]));
                }
            }
        }
    }

    const int r0 = lane >> 2;
    const int cp = (lane & 3) * 2;
    #pragma unroll
    for (int i = 0; i < 4; i++)
        #pragma unroll
        for (int j = 0; j < 4; j++) {
            int col = n0 + wn + j * 8 + cp;
            float2 bb = *(const float2*)(bias + col);
            int row = m0 + wm + i * 16 + r0;
            float2 o0 = make_float2(acc[i][j][0] + bb.x, acc[i][j][1] + bb.y);
            *(float2*)(C + (size_t)row * 256 + col) = o0;
            float2 o1 = make_float2(acc[i][j][2] + bb.x, acc[i][j][3] + bb.y);
            *(float2*)(C + (size_t)(row + 8) * 256 + col) = o1;
        }
}

// ====================== mma.sync flash attention (fp16) ====================
// MERGED SOFTMAX: KV processed 128 columns per iteration — S for both 64-col
// sub-tiles first (2x independent MMA chains), then ONE softmax chain over
// 128 cols, then all PV MMAs. Halves the serial softmax chains per block and
// doubles MMA-phase ILP (the R13/R14 neutral results showed attention is
// dependency-latency-bound, not pipe/barrier-bound).
// Dynamic smem: Qh @ 0 (10240); super-buf b @ 10240+b*20480
//   (two tiles x {K 5120, V 5120}). Total 51200.
#define ASM_QH 0
#define ASM_SB(b) (10240 + (b) * 20480)
#define ASM_TOTAL 51200

__global__ __launch_bounds__(256, 2)
void attn_mma_kernel(const __half* __restrict__ Qh_g,
                     const __half* __restrict__ Kh_g,
                     const __half* __restrict__ Vh_g,
                     __half* __restrict__ Og)
{
    extern __shared__ char smem[];
    const uint32_t sb = smem_u32(smem);
    const int tid  = threadIdx.x;
    const int wid  = tid >> 5;
    const int lane = tid & 31;
    const int tq = (int)gridDim.x - 1 - (int)blockIdx.x;   // long blocks first
    const int hb = blockIdx.y;
    const int h  = hb & 7;
    const int bb = hb >> 3;
    const size_t base = (size_t)bb * 2048 * 256 + (size_t)h * 32;
    const int qbase = tq * 128;
    __half* Ob = Og + base;

    const int nsuper = tq + 1;   // 128 KV cols per super-step

    // prologue: cp.async Q + KV cols [0,128) -> super-buf 0, one group
    #pragma unroll
    for (int g = 0; g < 2; g++) {
        int s = tid + g * 256, r = s >> 2, c8 = (s & 3) * 8;
        CP_ASYNC16(sb + ASM_QH + (r * 40 + c8) * 2,
                   Qh_g + base + (size_t)(qbase + r) * 256 + c8);
    }
    {
        int r = tid >> 2, c8 = (tid & 3) * 8;
        #pragma unroll
        for (int sub = 0; sub < 2; sub++) {
            size_t src = base + (size_t)(sub * 64 + r) * 256 + c8;
            uint32_t dst = sb + ASM_SB(0) + sub * 10240 + (r * 40 + c8) * 2;
            CP_ASYNC16(dst,        Kh_g + src);
            CP_ASYNC16(dst + 5120, Vh_g + src);
        }
    }
    CP_COMMIT();

    uint32_t qh[2][4];
    float o[4][4] = {};
    float mrow[2] = {-1e30f, -1e30f};   // log2 units
    float lrow[2] = {0.0f, 0.0f};

    const uint32_t kfoff = (((((lane >> 4) & 1) << 3) + (lane & 7)) * 40
                           + (((lane >> 3) & 1) << 3)) * 2;
    const uint32_t vfoff = 5120u + ((lane & 15) * 40 + (((lane >> 4) & 1) << 3)) * 2;

    for (int u = 0; u < nsuper; u++) {
        __syncthreads();   // all warps done reading super-buf (u+1)&1 (step u-1)
        if (u + 1 < nsuper) {
            const uint32_t sbuf = sb + ASM_SB((u + 1) & 1);
            int r = tid >> 2, c8 = (tid & 3) * 8;
            #pragma unroll
            for (int sub = 0; sub < 2; sub++) {
                size_t src = base + (size_t)((2 * (u + 1) + sub) * 64 + r) * 256 + c8;
                uint32_t dst = sbuf + sub * 10240 + (r * 40 + c8) * 2;
                CP_ASYNC16(dst,        Kh_g + src);
                CP_ASYNC16(dst + 5120, Vh_g + src);
            }
            CP_COMMIT();
            CP_WAIT1();    // super-step u (and Q on u==0) landed
        } else {
            CP_WAIT0();
        }
        __syncthreads();

        if (u == 0) {      // resident Q fragments
            const int arow = lane & 15;
            const int aco  = ((lane >> 4) << 3);
            #pragma unroll
            for (int ks = 0; ks < 2; ks++)
                LDSM_X4(qh[ks], sb + ASM_QH + ((wid * 16 + arow) * 40 + ks * 16 + aco) * 2);
        }

        const uint32_t kv0 = sb + ASM_SB(u & 1);
        const uint32_t kv1 = kv0 + 10240;

        // ---- S = Q @ K^T for 128 cols (two independent accumulator sets) ----
        float s[16][4] = {};
        #pragma unroll
        for (int ks = 0; ks < 2; ks++) {
            #pragma unroll
            for (int jp = 0; jp < 4; jp++) {
                uint32_t k4a[4], k4b[4];
                LDSM_X4(k4a, kv0 + kfoff + (jp * 16 * 40 + ks * 16) * 2);
                LDSM_X4(k4b, kv1 + kfoff + (jp * 16 * 40 + ks * 16) * 2);
                MMA16816(s[2 * jp],         qh[ks], (&k4a[0]));
                MMA16816(s[8 + 2 * jp],     qh[ks], (&k4b[0]));
                MMA16816(s[2 * jp + 1],     qh[ks], (&k4a[2]));
                MMA16816(s[8 + 2 * jp + 1], qh[ks], (&k4b[2]));
            }
        }

        // ---- causal mask (final 128-col slab only) ----
        if (u == nsuper - 1) {
            const int row0 = qbase + wid * 16 + (lane >> 2);
            #pragma unroll
            for (int j = 0; j < 16; j++) {
                int col = u * 128 + j * 8 + (lane & 3) * 2;
                if (col     > row0)     s[j][0] = -1e30f;
                if (col + 1 > row0)     s[j][1] = -1e30f;
                if (col     > row0 + 8) s[j][2] = -1e30f;
                if (col + 1 > row0 + 8) s[j][3] = -1e30f;
            }
        }

        // ---- ONE online softmax over 128 cols (base-2; ex2.f16x2) ----
        uint32_t p2[2][16];
        #pragma unroll
        for (int hf = 0; hf < 2; hf++) {
            const int a0 = 2 * hf, a1 = 2 * hf + 1;
            float mj[16];
            #pragma unroll
            for (int j = 0; j < 16; j++) mj[j] = fmaxf(s[j][a0], s[j][a1]);
            #pragma unroll
            for (int j = 0; j < 8; j++) mj[j] = fmaxf(mj[j], mj[j + 8]);
            mj[0] = fmaxf(mj[0], mj[1]); mj[2] = fmaxf(mj[2], mj[3]);
            mj[4] = fmaxf(mj[4], mj[5]); mj[6] = fmaxf(mj[6], mj[7]);
            mj[0] = fmaxf(mj[0], mj[2]); mj[4] = fmaxf(mj[4], mj[6]);
            float mt = fmaxf(mj[0], mj[4]);
            mt = fmaxf(mt, __shfl_xor_sync(0xffffffffu, mt, 1));
            mt = fmaxf(mt, __shfl_xor_sync(0xffffffffu, mt, 2));
            float mnew  = fmaxf(mrow[hf], mt);
            float alpha = ex2f(mrow[hf] - mnew);
            #pragma unroll
            for (int j = 0; j < 16; j++)
                p2[hf][j] = ex2_h2(s[j][a0] - mnew, s[j][a1] - mnew);
            __half2 t[8];
            #pragma unroll
            for (int j = 0; j < 8; j++)
                t[j] = __hadd2(u2h2(p2[hf][j]), u2h2(p2[hf][j + 8]));
            t[0] = __hadd2(t[0], t[1]); t[2] = __hadd2(t[2], t[3]);
            t[4] = __hadd2(t[4], t[5]); t[6] = __hadd2(t[6], t[7]);
            t[0] = __hadd2(t[0], t[2]); t[4] = __hadd2(t[4], t[6]);
            t[0] = __hadd2(t[0], t[4]);
            float ls = __low2float(t[0]) + __high2float(t[0]);
            ls += __shfl_xor_sync(0xffffffffu, ls, 1);
            ls += __shfl_xor_sync(0xffffffffu, ls, 2);
            mrow[hf] = mnew;
            lrow[hf] = lrow[hf] * alpha + ls;
            #pragma unroll
            for (int j = 0; j < 4; j++) {
                o[j][a0] *= alpha;
                o[j][a1] *= alpha;
            }
        }

        // ---- O += P @ V over 128 cols (P already packed; 8 k16 groups) ----
        #pragma unroll
        for (int t = 0; t < 8; t++) {
            uint32_t ph[4];
            ph[0] = p2[0][2 * t];
            ph[1] = p2[1][2 * t];
            ph[2] = p2[0][2 * t + 1];
            ph[3] = p2[1][2 * t + 1];

            const uint32_t kvv = (t < 4) ? kv0 : kv1;
            const int tt = t & 3;
            #pragma unroll
            for (int jp = 0; jp < 2; jp++) {
                uint32_t v4[4];
                LDSM_X4_T(v4, kvv + vfoff + (tt * 16 * 40 + jp * 16) * 2);
                MMA16816(o[2 * jp],     ph, (&v4[0]));
                MMA16816(o[2 * jp + 1], ph, (&v4[2]));
            }
        }
    }

    // ---- normalize + store (fp16) ----
    const float inv0 = 1.0f / lrow[0];
    const float inv1 = 1.0f / lrow[1];
    const int row = qbase + wid * 16 + (lane >> 2);
    #pragma unroll
    for (int j = 0; j < 4; j++) {
        int col = j * 8 + (lane & 3) * 2;
        *(uint32_t*)(Ob + (size_t)row * 256 + col) =
            pack_h(o[j][0] * inv0, o[j][1] * inv0);
        *(uint32_t*)(Ob + (size_t)(row + 8) * 256 + col) =
            pack_h(o[j][2] * inv1, o[j][3] * inv1);
    }
}

// ---------------------------------------------------------------------------
extern "C" void kernel_launch(void* const* d_in, const int* in_sizes, int n_in,
                              void* d_out, int out_size)
{
    const float* query = (const float*)d_in[0];
    const float* key   = (const float*)d_in[1];
    const float* value = (const float*)d_in[2];
    const float* Wq    = (const float*)d_in[3];
    const float* bq    = (const float*)d_in[4];
    const float* Wk    = (const float*)d_in[5];
    const float* bk    = (const float*)d_in[6];
    const float* Wv    = (const float*)d_in[7];
    const float* bv    = (const float*)d_in[8];
    const float* Wo    = (const float*)d_in[9];
    const float* bo    = (const float*)d_in[10];
    float* out = (float*)d_out;

    __half *AOh, *Qh, *Kh, *Vh, *Wh;
    cudaGetSymbolAddress((void**)&AOh, g_AOh);
    cudaGetSymbolAddress((void**)&Qh,  g_Qh);
    cudaGetSymbolAddress((void**)&Kh,  g_Kh);
    cudaGetSymbolAddress((void**)&Vh,  g_Vh);
    cudaGetSymbolAddress((void**)&Wh,  g_Wh);

    cudaFuncSetAttribute(gemm_qkv_kernel,
                         cudaFuncAttributeMaxDynamicSharedMemorySize, GSM_TOTAL);
    cudaFuncSetAttribute(gemm_out_kernel,
                         cudaFuncAttributeMaxDynamicSharedMemorySize, OSM_TOTAL);
    cudaFuncSetAttribute(attn_mma_kernel,
                         cudaFuncAttributeMaxDynamicSharedMemorySize, ASM_TOTAL);

    convert_w_kernel<<<dim3(256, 4), 256>>>(Wq, Wk, Wv, Wo, Wh);

    gemm_qkv_kernel<<<dim3(2, 128, 3), 256, GSM_TOTAL>>>(
        query, key, value, Wh, bq, bk, bv, Qh, Kh, Vh);

    attn_mma_kernel<<<dim3(16, 64), 256, ASM_TOTAL>>>(Qh, Kh, Vh, AOh);

    gemm_out_kernel<<<dim3(2, 128), 256, OSM_TOTAL>>>(
        AOh, Wh + 3 * 65536, bo, out);
}